// round 7
// baseline (speedup 1.0000x reference)
#include <cuda_runtime.h>
#include <cstdint>

// 12-bit ripple-carry adder over {0,1}-valued float32 arrays.
// A,B: [BATCH, 12] float32, col 11 = LSB (weight 2^(11-i)).
// Out: sums [BATCH,12] at d_out[0..B*12), carry [BATCH] at d_out[B*12..B*13).
//
// Warp-autonomous version: each warp owns 96 chunks = 32 rows. Thread l loads
// chunks wbase+l, +32, +64 (three contiguous 512B warp transactions), packs
// nibbles to smem, __syncwarp (no block barrier!), assembles its row, stores
// the 13-bit sum to smem, __syncwarp, scatters sum nibbles back to its three
// output chunks (contiguous stores). No __syncthreads -> warps never couple.
// __ldcs/__stcs evict-first (620MB stream, zero reuse).

__device__ __forceinline__ unsigned f2b(float x) {
    return __float_as_uint(x) != 0u ? 1u : 0u;   // x is exactly 0.0f or 1.0f
}

__device__ __forceinline__ unsigned pack_nib(float4 a, float4 b) {
    unsigned na = (f2b(a.x) << 3) | (f2b(a.y) << 2) | (f2b(a.z) << 1) | f2b(a.w);
    unsigned nb = (f2b(b.x) << 3) | (f2b(b.y) << 2) | (f2b(b.z) << 1) | f2b(b.w);
    return na | (nb << 4);
}

__device__ __forceinline__ float4 nib_to_f4(unsigned on) {
    float4 o;
    o.x = (on & 8u) ? 1.0f : 0.0f;
    o.y = (on & 4u) ? 1.0f : 0.0f;
    o.z = (on & 2u) ? 1.0f : 0.0f;
    o.w = (on & 1u) ? 1.0f : 0.0f;
    return o;
}

#define TPB 256
#define WARPS (TPB / 32)                    // 8
#define CHUNKS_PER_WARP 96                  // = 32 rows
#define CHUNKS_PER_BLOCK (WARPS * CHUNKS_PER_WARP)   // 768
#define ROWS_PER_BLOCK (CHUNKS_PER_BLOCK / 3)        // 256

// ---- Fast path: nchunks % CHUNKS_PER_BLOCK == 0, no bounds checks ----
__global__ void __launch_bounds__(TPB, 8) adder12_exact(
    const float4* __restrict__ A4,
    const float4* __restrict__ B4,
    float4* __restrict__ S4,
    float* __restrict__ carry)
{
    __shared__ unsigned nib[CHUNKS_PER_BLOCK];   // packed a|b nibbles
    __shared__ unsigned ssum[ROWS_PER_BLOCK];    // 13-bit row sums

    const int lane = threadIdx.x & 31;
    const int wid  = threadIdx.x >> 5;
    const int cb   = blockIdx.x * CHUNKS_PER_BLOCK + wid * CHUNKS_PER_WARP;
    const int woff = wid * CHUNKS_PER_WARP;      // warp's nib region
    const int roff = wid * 32;                   // warp's ssum region

    // Front-batched streaming loads (MLP 6), all warp-contiguous.
    float4 a0 = __ldcs(&A4[cb + lane]);
    float4 b0 = __ldcs(&B4[cb + lane]);
    float4 a1 = __ldcs(&A4[cb + 32 + lane]);
    float4 b1 = __ldcs(&B4[cb + 32 + lane]);
    float4 a2 = __ldcs(&A4[cb + 64 + lane]);
    float4 b2 = __ldcs(&B4[cb + 64 + lane]);

    nib[woff + lane]      = pack_nib(a0, b0);
    nib[woff + 32 + lane] = pack_nib(a1, b1);
    nib[woff + 64 + lane] = pack_nib(a2, b2);
    __syncwarp();

    // Row assembly: thread lane owns local row `lane` (chunks 3l,3l+1,3l+2).
    {
        unsigned c0 = nib[woff + 3 * lane + 0];
        unsigned c1 = nib[woff + 3 * lane + 1];
        unsigned c2 = nib[woff + 3 * lane + 2];
        unsigned av = ((c0 & 0xFu) << 8) | ((c1 & 0xFu) << 4) | (c2 & 0xFu);
        unsigned bv = ((c0 >> 4) << 8) | (((c1 >> 4) & 0xFu) << 4) | ((c2 >> 4) & 0xFu);
        unsigned s = av + bv;                    // 13-bit result
        ssum[roff + lane] = s;
        __stcs(&carry[blockIdx.x * ROWS_PER_BLOCK + roff + lane],
               (s >> 12) ? 1.0f : 0.0f);
    }
    __syncwarp();

    // Scatter: thread lane writes chunks wbase + m*32 + lane (contiguous).
#pragma unroll
    for (int m = 0; m < 3; m++) {
        int k = m * 32 + lane;                   // local chunk index in warp
        int row = k / 3;
        int part = k - row * 3;
        unsigned s = ssum[roff + row];
        unsigned on = (s >> (8 - 4 * part)) & 0xFu;
        __stcs(&S4[cb + m * 32 + lane], nib_to_f4(on));
    }
}

// ---- Guarded fallback for non-divisible sizes (block-barrier version) ----
__global__ void __launch_bounds__(TPB, 8) adder12_guarded(
    const float4* __restrict__ A4,
    const float4* __restrict__ B4,
    float4* __restrict__ S4,
    float* __restrict__ carry,
    int nchunks, int batch)
{
    __shared__ unsigned nib[CHUNKS_PER_BLOCK];

    const int tid = threadIdx.x;
    const int base = blockIdx.x * CHUNKS_PER_BLOCK + tid;

    bool v[3];
    float4 a[3], b[3];
#pragma unroll
    for (int k = 0; k < 3; k++) {
        int ci = base + k * TPB;
        v[k] = (ci < nchunks);
        if (v[k]) { a[k] = __ldcs(&A4[ci]); b[k] = __ldcs(&B4[ci]); }
    }
#pragma unroll
    for (int k = 0; k < 3; k++)
        nib[tid + k * TPB] = v[k] ? pack_nib(a[k], b[k]) : 0u;
    __syncthreads();

#pragma unroll
    for (int k = 0; k < 3; k++) {
        int li = tid + k * TPB;
        int lrow = li / 3;
        int part = li - lrow * 3;
        unsigned c0 = nib[lrow * 3 + 0], c1 = nib[lrow * 3 + 1], c2 = nib[lrow * 3 + 2];
        unsigned av = ((c0 & 0xFu) << 8) | ((c1 & 0xFu) << 4) | (c2 & 0xFu);
        unsigned bv = ((c0 >> 4) << 8) | (((c1 >> 4) & 0xFu) << 4) | ((c2 >> 4) & 0xFu);
        unsigned s = av + bv;
        if (v[k]) __stcs(&S4[base + k * TPB],
                         nib_to_f4((s >> (8 - 4 * part)) & 0xFu));
    }

    {
        int row = blockIdx.x * ROWS_PER_BLOCK + tid;
        if (tid < ROWS_PER_BLOCK && row < batch) {
            unsigned c0 = nib[tid * 3 + 0], c1 = nib[tid * 3 + 1], c2 = nib[tid * 3 + 2];
            unsigned av = ((c0 & 0xFu) << 8) | ((c1 & 0xFu) << 4) | (c2 & 0xFu);
            unsigned bv = ((c0 >> 4) << 8) | (((c1 >> 4) & 0xFu) << 4) | ((c2 >> 4) & 0xFu);
            unsigned s = av + bv;
            __stcs(&carry[row], (s >> 12) ? 1.0f : 0.0f);
        }
    }
}

extern "C" void kernel_launch(void* const* d_in, const int* in_sizes, int n_in,
                              void* d_out, int out_size) {
    const float* A = (const float*)d_in[0];
    const float* B = (const float*)d_in[1];
    float* out = (float*)d_out;

    int batch = in_sizes[0] / 12;
    int nchunks = batch * 3;

    float* sums = out;
    float* carry = out + (long)batch * 12;

    if (nchunks % CHUNKS_PER_BLOCK == 0) {
        int blocks = nchunks / CHUNKS_PER_BLOCK;
        adder12_exact<<<blocks, TPB>>>(
            (const float4*)A, (const float4*)B, (float4*)sums, carry);
    } else {
        int blocks = (nchunks + CHUNKS_PER_BLOCK - 1) / CHUNKS_PER_BLOCK;
        adder12_guarded<<<blocks, TPB>>>(
            (const float4*)A, (const float4*)B, (float4*)sums, carry,
            nchunks, batch);
    }
}